// round 13
// baseline (speedup 1.0000x reference)
#include <cuda_runtime.h>
#include <cuda_fp16.h>
#include <cstdint>

#define N_ 32
#define C_ 16
#define H_ 256
#define W_ 256
#define HW_ (H_ * W_)
#define CHW_ (C_ * H_ * W_)
#define P_ 2000000

// 64 MB NHWC fp16 scratch: one 32B texel (16 halves) per (n,h,w), 32B-aligned.
struct __align__(32) Texel8 { uint32_t u[8]; };
__device__ Texel8 g_tex[(size_t)N_ * HW_];

__device__ __forceinline__ uint32_t pack_h2(float a, float b) {
    __half2 h = __floats2half2_rn(a, b);
    return *reinterpret_cast<uint32_t*>(&h);
}

// 256-bit texel store, L2 evict-last (R10 transpose, 27.6us — keep).
__device__ __forceinline__ void st_texel(Texel8* p, const uint32_t r[8]) {
    asm volatile("st.global.L2::evict_last.v8.u32 [%0], {%1,%2,%3,%4,%5,%6,%7,%8};"
                 :: "l"(p), "r"(r[0]), "r"(r[1]), "r"(r[2]), "r"(r[3]),
                    "r"(r[4]), "r"(r[5]), "r"(r[6]), "r"(r[7]) : "memory");
}

__global__ void __launch_bounds__(256) transpose_to_nhwc_h(const float* __restrict__ in) {
    int idx = blockIdx.x * blockDim.x + threadIdx.x;   // texel: n*HW + h*W + w
    if (idx >= N_ * HW_) return;
    int n  = idx >> 16;
    int hw = idx & (HW_ - 1);
    const float* src = in + (size_t)n * CHW_ + hw;
    float v[C_];
#pragma unroll
    for (int c = 0; c < C_; c++) v[c] = __ldcs(src + c * HW_);

    uint32_t r[8];
#pragma unroll
    for (int j = 0; j < 8; j++) r[j] = pack_h2(v[2 * j], v[2 * j + 1]);
    st_texel(&g_tex[idx], r);
}

__device__ __forceinline__ uint32_t smem_u32(const void* p) {
    uint32_t a;
    asm("{ .reg .u64 t; cvta.to.shared.u64 t, %1; cvt.u32.u64 %0, t; }"
        : "=r"(a) : "l"(p));
    return a;
}

// 4 lanes per point, 4 points per group, cp.async staging: 16 outstanding
// 8B loads per thread with NO register cost for in-flight data.
// Stage layout [slot][thread]: cp.async writes and LDS reads are both
// warp-contiguous 256B (conflict-free). No block sync needed — each thread
// consumes only its own column.
__global__ void __launch_bounds__(256) gather_bilinear_cp(
    const float2* __restrict__ grid,
    const int* __restrict__ indices,
    float* __restrict__ out)
{
    __shared__ uint2 stage[16][256];   // 32 KB

    int t = blockIdx.x * blockDim.x + threadIdx.x;
    int grp = t >> 2;            // points 4*grp .. 4*grp+3
    int i   = t & 3;             // channel chunk
    if (grp >= P_ / 4) return;

    float4 ga = __ldcs(reinterpret_cast<const float4*>(grid) + 2 * grp);
    float4 gb = __ldcs(reinterpret_cast<const float4*>(grid) + 2 * grp + 1);
    int4   nn = __ldcs(reinterpret_cast<const int4*>(indices) + grp);

    const uint2* tex = reinterpret_cast<const uint2*>(g_tex);
    float w[4][4];

#pragma unroll
    for (int k = 0; k < 4; k++) {
        float gx = (k == 0) ? ga.x : (k == 1) ? ga.z : (k == 2) ? gb.x : gb.z;
        float gy = (k == 0) ? ga.y : (k == 1) ? ga.w : (k == 2) ? gb.y : gb.w;
        int   n  = ((k == 0) ? nn.x : (k == 1) ? nn.y : (k == 2) ? nn.z : nn.w) & (N_ - 1);

        float x = (gx + 1.0f) * 0.5f * (float)(W_ - 1);
        float y = (gy + 1.0f) * 0.5f * (float)(H_ - 1);
        float x0f = floorf(x);
        float y0f = floorf(y);
        float wx = x - x0f;
        float wy = y - y0f;
        int x0 = (int)x0f, y0 = (int)y0f;
        int x1 = x0 + 1,   y1 = y0 + 1;

        bool vx0 = (x0 >= 0) & (x0 <= W_ - 1);
        bool vx1 = (x1 >= 0) & (x1 <= W_ - 1);
        bool vy0 = (y0 >= 0) & (y0 <= H_ - 1);
        bool vy1 = (y1 >= 0) & (y1 <= H_ - 1);

        int x0c = min(max(x0, 0), W_ - 1);
        int x1c = min(max(x1, 0), W_ - 1);
        int y0c = min(max(y0, 0), H_ - 1);
        int y1c = min(max(y1, 0), H_ - 1);

        w[k][0] = (1.0f - wx) * (1.0f - wy) * (float)(vx0 && vy0);
        w[k][1] = wx * (1.0f - wy) * (float)(vx1 && vy0);
        w[k][2] = (1.0f - wx) * wy * (float)(vx0 && vy1);
        w[k][3] = wx * wy * (float)(vx1 && vy1);

        uint32_t base = (uint32_t)n * (HW_ * 4) + i;
        uint32_t o0 = base + (y0c * W_ + x0c) * 4;
        uint32_t o1 = base + (y0c * W_ + x1c) * 4;
        uint32_t o2 = base + (y1c * W_ + x0c) * 4;
        uint32_t o3 = base + (y1c * W_ + x1c) * 4;

        uint32_t d0 = smem_u32(&stage[k * 4 + 0][threadIdx.x]);
        uint32_t d1 = smem_u32(&stage[k * 4 + 1][threadIdx.x]);
        uint32_t d2 = smem_u32(&stage[k * 4 + 2][threadIdx.x]);
        uint32_t d3 = smem_u32(&stage[k * 4 + 3][threadIdx.x]);

        asm volatile("cp.async.ca.shared.global [%0], [%1], 8;" :: "r"(d0), "l"(tex + o0));
        asm volatile("cp.async.ca.shared.global [%0], [%1], 8;" :: "r"(d1), "l"(tex + o1));
        asm volatile("cp.async.ca.shared.global [%0], [%1], 8;" :: "r"(d2), "l"(tex + o2));
        asm volatile("cp.async.ca.shared.global [%0], [%1], 8;" :: "r"(d3), "l"(tex + o3));
    }

    asm volatile("cp.async.commit_group;" ::: "memory");
    asm volatile("cp.async.wait_group 0;" ::: "memory");

#pragma unroll
    for (int k = 0; k < 4; k++) {
        uint2 r0 = stage[k * 4 + 0][threadIdx.x];
        uint2 r1 = stage[k * 4 + 1][threadIdx.x];
        uint2 r2 = stage[k * 4 + 2][threadIdx.x];
        uint2 r3 = stage[k * 4 + 3][threadIdx.x];

        float2 a0 = __half22float2(*reinterpret_cast<__half2*>(&r0.x));
        float2 b0 = __half22float2(*reinterpret_cast<__half2*>(&r0.y));
        float2 a1 = __half22float2(*reinterpret_cast<__half2*>(&r1.x));
        float2 b1 = __half22float2(*reinterpret_cast<__half2*>(&r1.y));
        float2 a2 = __half22float2(*reinterpret_cast<__half2*>(&r2.x));
        float2 b2 = __half22float2(*reinterpret_cast<__half2*>(&r2.y));
        float2 a3 = __half22float2(*reinterpret_cast<__half2*>(&r3.x));
        float2 b3 = __half22float2(*reinterpret_cast<__half2*>(&r3.y));

        float4 res;
        res.x = w[k][0] * a0.x + w[k][1] * a1.x + w[k][2] * a2.x + w[k][3] * a3.x;
        res.y = w[k][0] * a0.y + w[k][1] * a1.y + w[k][2] * a2.y + w[k][3] * a3.y;
        res.z = w[k][0] * b0.x + w[k][1] * b1.x + w[k][2] * b2.x + w[k][3] * b3.x;
        res.w = w[k][0] * b0.y + w[k][1] * b1.y + w[k][2] * b2.y + w[k][3] * b3.y;

        __stcs(reinterpret_cast<float4*>(out) + (size_t)(4 * grp + k) * 4 + i, res);
    }
}

extern "C" void kernel_launch(void* const* d_in, const int* in_sizes, int n_in,
                              void* d_out, int out_size) {
    const float*  input   = (const float*)d_in[0];
    const float2* grid    = (const float2*)d_in[1];
    const int*    indices = (const int*)d_in[2];
    float*        out     = (float*)d_out;

    {
        int total = N_ * HW_;
        int threads = 256;
        int blocks = (total + threads - 1) / threads;
        transpose_to_nhwc_h<<<blocks, threads>>>(input);
    }
    {
        long long total = (long long)(P_ / 4) * 4;   // 4 lanes per 4-point group
        int threads = 256;
        int blocks = (int)((total + threads - 1) / threads);
        gather_bilinear_cp<<<blocks, threads>>>(grid, indices, out);
    }
}

// round 14
// speedup vs baseline: 1.0759x; 1.0759x over previous
#include <cuda_runtime.h>
#include <cuda_fp16.h>
#include <cstdint>

#define N_ 32
#define C_ 16
#define H_ 256
#define W_ 256
#define HW_ (H_ * W_)
#define CHW_ (C_ * H_ * W_)
#define P_ 2000000

// 64 MB NHWC fp16 scratch: one 32B texel (16 halves) per (n,h,w), 32B-aligned.
// +1 pad texel: the x0==W-1 corner case (weight exactly 0) pair-loads 32B past
// the last texel; pad keeps it in bounds. __device__ globals are zero-init.
struct __align__(32) Texel8 { uint32_t u[8]; };
__device__ Texel8 g_tex[(size_t)N_ * HW_ + 1];

__device__ __forceinline__ uint32_t pack_h2(float a, float b) {
    __half2 h = __floats2half2_rn(a, b);
    return *reinterpret_cast<uint32_t*>(&h);
}

// 256-bit texel store, L2 evict-last (R10 transpose, 27.6us — keep).
__device__ __forceinline__ void st_texel(Texel8* p, const uint32_t r[8]) {
    asm volatile("st.global.L2::evict_last.v8.u32 [%0], {%1,%2,%3,%4,%5,%6,%7,%8};"
                 :: "l"(p), "r"(r[0]), "r"(r[1]), "r"(r[2]), "r"(r[3]),
                    "r"(r[4]), "r"(r[5]), "r"(r[6]), "r"(r[7]) : "memory");
}

__global__ void __launch_bounds__(256) transpose_to_nhwc_h(const float* __restrict__ in) {
    int idx = blockIdx.x * blockDim.x + threadIdx.x;   // texel: n*HW + h*W + w
    if (idx >= N_ * HW_) return;
    int n  = idx >> 16;
    int hw = idx & (HW_ - 1);
    const float* src = in + (size_t)n * CHW_ + hw;
    float v[C_];
#pragma unroll
    for (int c = 0; c < C_; c++) v[c] = __ldcs(src + c * HW_);

    uint32_t r[8];
#pragma unroll
    for (int j = 0; j < 8; j++) r[j] = pack_h2(v[2 * j], v[2 * j + 1]);
    st_texel(&g_tex[idx], r);
}

// 8 lanes per point-PAIR-side: group of 8 lanes handles 2 points.
// Lane l: side s=(l>>2) (x0/x1 texel of the 64B row pair, also the point this
// lane computes coords for), chunk c=(l&3). Each x-row pair (y,x0)+(y,x1) is
// 64B contiguous -> a warp load-instr touches ~5 lines instead of 8.
// Coord math once per point; bases/weights/partials exchanged via shfl_xor(4).
__global__ void __launch_bounds__(256) gather_bilinear_pair(
    const float2* __restrict__ grid,
    const int* __restrict__ indices,
    float* __restrict__ out)
{
    int t = blockIdx.x * blockDim.x + threadIdx.x;
    int grp = t >> 3;            // handles points 2*grp, 2*grp+1
    int l   = t & 7;
    int s   = l >> 2;            // my side == my owned point (0/1)
    if (grp >= P_ / 2) return;   // exact grid: never taken, shuffles all-active

    int p = 2 * grp + s;         // point whose coords this lane computes
    float2 g = __ldg(grid + p);
    int n = __ldg(indices + p) & (N_ - 1);

    float x = (g.x + 1.0f) * 0.5f * (float)(W_ - 1);
    float y = (g.y + 1.0f) * 0.5f * (float)(H_ - 1);
    float x0f = floorf(x);
    float y0f = floorf(y);
    float wx = x - x0f;
    float wy = y - y0f;
    int x0 = (int)x0f, y0 = (int)y0f;
    int x1 = x0 + 1,   y1 = y0 + 1;

    bool vx0 = (x0 >= 0) & (x0 <= W_ - 1);
    bool vx1 = (x1 >= 0) & (x1 <= W_ - 1);
    bool vy0 = (y0 >= 0) & (y0 <= H_ - 1);
    bool vy1 = (y1 >= 0) & (y1 <= H_ - 1);

    int x0c = min(max(x0, 0), W_ - 1);
    int y0c = min(max(y0, 0), H_ - 1);
    int y1c = min(max(y1, 0), H_ - 1);

    float w00 = (1.0f - wx) * (1.0f - wy) * (float)(vx0 && vy0);
    float w01 = wx * (1.0f - wy) * (float)(vx1 && vy0);
    float w10 = (1.0f - wx) * wy * (float)(vx0 && vy1);
    float w11 = wx * wy * (float)(vx1 && vy1);

    // pair-row bases in uint2 units (texel = 4 uint2); pair = [x0c, x0c+1]
    uint32_t b0 = ((uint32_t)n * HW_ + y0c * W_ + x0c) * 4;   // my point, y0 row
    uint32_t b1 = ((uint32_t)n * HW_ + y1c * W_ + x0c) * 4;   // my point, y1 row

    // exchange bases with partner lane (owner of the other point)
    uint32_t b0o = __shfl_xor_sync(0xFFFFFFFFu, b0, 4);
    uint32_t b1o = __shfl_xor_sync(0xFFFFFFFFu, b1, 4);

    // exchange weights: partner (side 1-s) needs side-(1-s) weights of MY point;
    // I receive side-s weights of the other point.
    float rcv_y0 = __shfl_xor_sync(0xFFFFFFFFu, s ? w00 : w01, 4);
    float rcv_y1 = __shfl_xor_sync(0xFFFFFFFFu, s ? w10 : w11, 4);
    float own_y0 = s ? w01 : w00;    // my-side weights of my point
    float own_y1 = s ? w11 : w10;

    // order by point id
    uint32_t b0_p0 = s ? b0o : b0;   // point0 y0 pair base
    uint32_t b1_p0 = s ? b1o : b1;
    uint32_t b0_p1 = s ? b0  : b0o;
    uint32_t b1_p1 = s ? b1  : b1o;
    float w0_y0 = s ? rcv_y0 : own_y0;   // point0, my side, y0-row weight
    float w0_y1 = s ? rcv_y1 : own_y1;
    float w1_y0 = s ? own_y0 : rcv_y0;
    float w1_y1 = s ? own_y1 : rcv_y1;

    const uint2* tex = reinterpret_cast<const uint2*>(g_tex);
    // lane l reads uint2 #l of each 64B pair row (side s, chunk c)
    uint2 r0a = __ldg(tex + b0_p0 + l);   // point0, y0
    uint2 r0b = __ldg(tex + b1_p0 + l);   // point0, y1
    uint2 r1a = __ldg(tex + b0_p1 + l);   // point1, y0
    uint2 r1b = __ldg(tex + b1_p1 + l);   // point1, y1

    float2 a0 = __half22float2(*reinterpret_cast<__half2*>(&r0a.x));
    float2 a1 = __half22float2(*reinterpret_cast<__half2*>(&r0a.y));
    float2 b0f = __half22float2(*reinterpret_cast<__half2*>(&r0b.x));
    float2 b1f = __half22float2(*reinterpret_cast<__half2*>(&r0b.y));
    float2 c0 = __half22float2(*reinterpret_cast<__half2*>(&r1a.x));
    float2 c1 = __half22float2(*reinterpret_cast<__half2*>(&r1a.y));
    float2 d0 = __half22float2(*reinterpret_cast<__half2*>(&r1b.x));
    float2 d1 = __half22float2(*reinterpret_cast<__half2*>(&r1b.y));

    // my-side partial contribution to each point (float4 over chunk c)
    float4 part0, part1;
    part0.x = w0_y0 * a0.x + w0_y1 * b0f.x;
    part0.y = w0_y0 * a0.y + w0_y1 * b0f.y;
    part0.z = w0_y0 * a1.x + w0_y1 * b1f.x;
    part0.w = w0_y0 * a1.y + w0_y1 * b1f.y;
    part1.x = w1_y0 * c0.x + w1_y1 * d0.x;
    part1.y = w1_y0 * c0.y + w1_y1 * d0.y;
    part1.z = w1_y0 * c1.x + w1_y1 * d1.x;
    part1.w = w1_y0 * c1.y + w1_y1 * d1.y;

    // send the partial of the partner's point; receive other side of mine
    float4 snd = s ? part0 : part1;
    float4 own = s ? part1 : part0;
    float4 res;
    res.x = own.x + __shfl_xor_sync(0xFFFFFFFFu, snd.x, 4);
    res.y = own.y + __shfl_xor_sync(0xFFFFFFFFu, snd.y, 4);
    res.z = own.z + __shfl_xor_sync(0xFFFFFFFFu, snd.z, 4);
    res.w = own.w + __shfl_xor_sync(0xFFFFFFFFu, snd.w, 4);

    // (2*grp+s)*4 + c == t: perfectly linear float4 store
    __stcs(reinterpret_cast<float4*>(out) + t, res);
}

extern "C" void kernel_launch(void* const* d_in, const int* in_sizes, int n_in,
                              void* d_out, int out_size) {
    const float*  input   = (const float*)d_in[0];
    const float2* grid    = (const float2*)d_in[1];
    const int*    indices = (const int*)d_in[2];
    float*        out     = (float*)d_out;

    {
        int total = N_ * HW_;
        int threads = 256;
        int blocks = (total + threads - 1) / threads;
        transpose_to_nhwc_h<<<blocks, threads>>>(input);
    }
    {
        long long total = (long long)(P_ / 2) * 8;   // 8 lanes per 2-point group
        int threads = 256;
        int blocks = (int)((total + threads - 1) / threads);
        gather_bilinear_pair<<<blocks, threads>>>(grid, indices, out);
    }
}